// round 14
// baseline (speedup 1.0000x reference)
#include <cuda_runtime.h>
#include <cuda_fp16.h>
#include <cstdint>

// Problem constants (GLALayer: B=4, T=4096, D_MODEL=1024, H=16, S=64)
#define D_MODEL 1024
#define T_LEN   4096
#define BATCH   4
#define M_TOT   (BATCH * T_LEN)   // 16384
#define HS      1024
#define NGATES  2048

#define NSEG    16
#define SEGLEN  (T_LEN / NSEG)    // 256

// Scratch (device globals)
__device__ __half g_gates[(size_t)M_TOT * NGATES];
__device__ __half g_v[(size_t)M_TOT * HS];
__device__ __half g_hl[(size_t)M_TOT * HS];     // fp16 local h (segment scan)
__device__ __half g_pc[(size_t)M_TOT * HS];     // fp16 cumulative prod of a
__device__ __half g_hh[(size_t)M_TOT * HS];     // fp16 final h (GEMM2 input)
__device__ __half g_xh[(size_t)M_TOT * D_MODEL];
__device__ __half g_gwh[(size_t)NGATES * D_MODEL];
__device__ __half g_vwh[(size_t)HS * D_MODEL];
__device__ __half g_owh[(size_t)D_MODEL * HS];
__device__ float g_segP[BATCH * NSEG * HS];
__device__ float g_segH[BATCH * NSEG * HS];
__device__ float g_segS[BATCH * NSEG * HS];

// ---------------------------------------------------------------------------
__device__ __forceinline__ uint32_t smem_u32(const void* p) {
    uint32_t a;
    asm("{ .reg .u64 t; cvta.to.shared.u64 t, %1; cvt.u32.u64 %0, t; }"
        : "=r"(a) : "l"(p));
    return a;
}

__device__ __forceinline__ void cpasync16(uint32_t dst, const void* src) {
    asm volatile("cp.async.cg.shared.global [%0], [%1], 16;" :: "r"(dst), "l"(src));
}
#define CP_COMMIT()  asm volatile("cp.async.commit_group;" ::: "memory")
#define CP_WAIT(n)   asm volatile("cp.async.wait_group %0;" :: "n"(n) : "memory")

// byte-offset swizzle (rows of 64 B) — R7 proven layout
__device__ __forceinline__ uint32_t sw64(uint32_t o) {
    return o ^ ((o >> 3) & 0x70);
}

__device__ __forceinline__ void mma_f16(float* c, const uint32_t* a, const uint32_t* b) {
    asm volatile(
        "mma.sync.aligned.m16n8k16.row.col.f32.f16.f16.f32 "
        "{%0,%1,%2,%3}, {%4,%5,%6,%7}, {%8,%9}, {%0,%1,%2,%3};"
        : "+f"(c[0]), "+f"(c[1]), "+f"(c[2]), "+f"(c[3])
        : "r"(a[0]), "r"(a[1]), "r"(a[2]), "r"(a[3]),
          "r"(b[0]), "r"(b[1]));
}

// ---------------------------------------------------------------------------
// TN GEMM fp16 mma.sync, fused dual-output.
// CTA 128x128 tile, 256 thr, 8 warps (2x4), warp tile 64x32.
// R7 mainloop: 4-stage cp.async, 32-half K stage, scalar fragment LDS.
// ---------------------------------------------------------------------------
#define KTH       32
#define STG_BYTES (128 * 64)         // 8192 per operand stage
#define NSTAGE    4
// dyn smem: NSTAGE * STG_BYTES * 2 = 65536 B

template<bool HALF_OUT>
__global__ void __launch_bounds__(256, 2)
gemm_f16_mma(const __half* __restrict__ A,
             const __half* __restrict__ B1, const __half* __restrict__ B2,
             void* __restrict__ C1, void* __restrict__ C2,
             int nsplit, int N1, int N2, int K) {
    extern __shared__ char smem[];
    const uint32_t sA_u = smem_u32(smem);
    const uint32_t sB_u = sA_u + NSTAGE * STG_BYTES;

    const int tid = threadIdx.x;
    const int lane = tid & 31;
    const int wid = tid >> 5;
    const int wm = (wid >> 2) * 64;   // 2 warps in M
    const int wn = (wid & 3) * 32;    // 4 warps in N
    const int g = lane >> 2;
    const int tg = lane & 3;

    const int bx = blockIdx.x, by = blockIdx.y;

    const __half* Bb;
    void* Cout;
    int Nout, colbase;
    if (bx < nsplit) {
        Bb = B1 + (size_t)bx * 128 * K;
        Cout = C1; Nout = N1; colbase = bx * 128;
    } else {
        Bb = B2 + (size_t)(bx - nsplit) * 128 * K;
        Cout = C2; Nout = N2; colbase = (bx - nsplit) * 128;
    }
    const __half* Ab = A + (size_t)by * 128 * K;

    float acc[4][4][4];
#pragma unroll
    for (int mi = 0; mi < 4; mi++)
#pragma unroll
        for (int ni = 0; ni < 4; ni++)
#pragma unroll
            for (int q = 0; q < 4; q++) acc[mi][ni][q] = 0.0f;

    const int NT = K / KTH;

    // stage load: 512 x 16B granules per operand over 256 threads = 2 each
    auto issue_stage = [&](int kt) {
        const int kof = kt * KTH;
        const uint32_t soff = (uint32_t)((kt & (NSTAGE - 1)) * STG_BYTES);
#pragma unroll
        for (int i = 0; i < 2; i++) {
            const int gid = tid + i * 256;      // 0..511
            const int row = gid >> 2;
            const int q = gid & 3;
            const uint32_t d = soff + sw64((uint32_t)(row * 64 + q * 16));
            cpasync16(sA_u + d, Ab + (size_t)row * K + kof + q * 8);
            cpasync16(sB_u + d, Bb + (size_t)row * K + kof + q * 8);
        }
        CP_COMMIT();
    };

    issue_stage(0);
    issue_stage(1);
    issue_stage(2);

    for (int kt = 0; kt < NT; kt++) {
        CP_WAIT(2);
        __syncthreads();

        const uint32_t aoff = sA_u + (uint32_t)((kt & (NSTAGE - 1)) * STG_BYTES);
        const uint32_t boff = sB_u + (uint32_t)((kt & (NSTAGE - 1)) * STG_BYTES);
#pragma unroll
        for (int ks = 0; ks < 2; ks++) {
            const int kb = ks * 32;             // 16 halfs = 32 B
            uint32_t af[4][4], bf[4][2];
#pragma unroll
            for (int mi = 0; mi < 4; mi++) {
                const int r = (wm + mi * 16 + g) * 64;
                const uint32_t o0 = (uint32_t)(r + kb + 4 * tg);
                af[mi][0] = *(const uint32_t*)__cvta_shared_to_generic(aoff + sw64(o0));
                af[mi][1] = *(const uint32_t*)__cvta_shared_to_generic(aoff + sw64(o0 + 512));
                af[mi][2] = *(const uint32_t*)__cvta_shared_to_generic(aoff + sw64(o0 + 16));
                af[mi][3] = *(const uint32_t*)__cvta_shared_to_generic(aoff + sw64(o0 + 528));
            }
#pragma unroll
            for (int ni = 0; ni < 4; ni++) {
                const int r = (wn + ni * 8 + g) * 64;
                const uint32_t o0 = (uint32_t)(r + kb + 4 * tg);
                bf[ni][0] = *(const uint32_t*)__cvta_shared_to_generic(boff + sw64(o0));
                bf[ni][1] = *(const uint32_t*)__cvta_shared_to_generic(boff + sw64(o0 + 16));
            }
#pragma unroll
            for (int mi = 0; mi < 4; mi++)
#pragma unroll
                for (int ni = 0; ni < 4; ni++)
                    mma_f16(acc[mi][ni], af[mi], bf[ni]);
        }
        __syncthreads();
        if (kt + 3 < NT) issue_stage(kt + 3);
    }

    // Epilogue
#pragma unroll
    for (int mi = 0; mi < 4; mi++) {
        const int row0 = by * 128 + wm + mi * 16 + g;
#pragma unroll
        for (int ni = 0; ni < 4; ni++) {
            const int col = colbase + wn + ni * 8 + 2 * tg;
            if (HALF_OUT) {
                __half* Ch = (__half*)Cout;
                *(__half2*)(Ch + (size_t)row0 * Nout + col) =
                    __floats2half2_rn(acc[mi][ni][0], acc[mi][ni][1]);
                *(__half2*)(Ch + (size_t)(row0 + 8) * Nout + col) =
                    __floats2half2_rn(acc[mi][ni][2], acc[mi][ni][3]);
            } else {
                float* Cf = (float*)Cout;
                *(float2*)(Cf + (size_t)row0 * Nout + col) =
                    make_float2(acc[mi][ni][0], acc[mi][ni][1]);
                *(float2*)(Cf + (size_t)(row0 + 8) * Nout + col) =
                    make_float2(acc[mi][ni][2], acc[mi][ni][3]);
            }
        }
    }
}

// ---------------------------------------------------------------------------
// One fused f32 -> f16 conversion over all four source arrays.
// ---------------------------------------------------------------------------
#define CVT_N_X   ((M_TOT * D_MODEL) / 2)
#define CVT_N_GW  ((NGATES * D_MODEL) / 2)
#define CVT_N_VW  ((HS * D_MODEL) / 2)
#define CVT_N_OW  ((D_MODEL * HS) / 2)

__global__ void convert_all(const float* __restrict__ x,
                            const float* __restrict__ gw,
                            const float* __restrict__ vw,
                            const float* __restrict__ ow) {
    int i = blockIdx.x * blockDim.x + threadIdx.x;
    const float* src;
    __half* dst;
    int off;
    if (i < CVT_N_X) {
        src = x; dst = g_xh; off = i;
    } else if (i < CVT_N_X + CVT_N_GW) {
        src = gw; dst = g_gwh; off = i - CVT_N_X;
    } else if (i < CVT_N_X + CVT_N_GW + CVT_N_VW) {
        src = vw; dst = g_vwh; off = i - CVT_N_X - CVT_N_GW;
    } else if (i < CVT_N_X + CVT_N_GW + CVT_N_VW + CVT_N_OW) {
        src = ow; dst = g_owh; off = i - CVT_N_X - CVT_N_GW - CVT_N_VW;
    } else {
        return;
    }
    float2 v = ((const float2*)src)[off];
    ((__half2*)dst)[off] = __floats2half2_rn(v.x, v.y);
}

// ---------------------------------------------------------------------------
// Segmented scan pass 1 (fused sigmoid). a/bg/h/P all fp32 in-register;
// stores local h and cumulative a-product as fp16 for the elementwise fixup.
// ---------------------------------------------------------------------------
__global__ void scan_pass1(const float* __restrict__ gate_b) {
    int idx = blockIdx.x * blockDim.x + threadIdx.x;   // 0..65535
    int j = idx & 1023;
    int s = (idx >> 10) & (NSEG - 1);
    int b = idx >> (10 + 4);
    size_t row0 = (size_t)b * T_LEN + (size_t)s * SEGLEN;
    const __half* gp = g_gates + row0 * NGATES + j;
    const __half* vp = g_v + (row0 << 10) + j;
    __half* hl = g_hl + (row0 << 10) + j;
    __half* pc = g_pc + (row0 << 10) + j;
    const float bfg = gate_b[j];
    const float big = gate_b[HS + j];
    float h = 0.0f, P = 1.0f;
#pragma unroll 4
    for (int t = 0; t < SEGLEN; t++) {
        float gf = __half2float(gp[(size_t)t * NGATES]) + bfg;
        float gi = __half2float(gp[(size_t)t * NGATES + HS]) + big;
        float a = 1.0f / (1.0f + __expf(-gf));
        float bg = 1.0f / (1.0f + __expf(-gi));
        float bv = bg * __half2float(vp[(size_t)t << 10]);
        h = fmaf(a, h, bv);
        P *= a;
        hl[(size_t)t << 10] = __float2half_rn(h);
        pc[(size_t)t << 10] = __float2half_rn(P);
    }
    g_segP[idx] = P;
    g_segH[idx] = h;
}

// ---------------------------------------------------------------------------
// Pass 2: resolve segment start states sequentially (tiny) + h_last output.
// ---------------------------------------------------------------------------
__global__ void scan_pass2(const float* __restrict__ h0,
                           float* __restrict__ hlast) {
    int idx = blockIdx.x * blockDim.x + threadIdx.x;   // 0..4095
    int b = idx >> 10;
    int j = idx & 1023;
    float hs = h0[idx];
#pragma unroll
    for (int s = 0; s < NSEG; s++) {
        int k = ((b * NSEG + s) << 10) + j;
        g_segS[k] = hs;
        hs = fmaf(g_segP[k], hs, g_segH[k]);
    }
    if (hlast) hlast[idx] = hs;
}

// ---------------------------------------------------------------------------
// Pass 3: pure elementwise fixup, vectorized half2:
//   h_t = h_local_t + Pcum_t * h_segstart   -> fp16 for GEMM2.
// ---------------------------------------------------------------------------
__global__ void scan_pass3() {
    int i = blockIdx.x * blockDim.x + threadIdx.x;   // over half2 elements
    if (i >= M_TOT * (HS / 2)) return;
    int row = i >> 9;               // 0..16383
    int jp = i & 511;               // half2 pair index
    int b = row >> 12;
    int s = (row >> 8) & (NSEG - 1);
    float2 hs2 = *(const float2*)(g_segS + (((size_t)(b * NSEG + s)) << 10) + jp * 2);
    float2 hl = __half22float2(((const __half2*)g_hl)[i]);
    float2 p  = __half22float2(((const __half2*)g_pc)[i]);
    ((__half2*)g_hh)[i] = __floats2half2_rn(fmaf(p.x, hs2.x, hl.x),
                                            fmaf(p.y, hs2.y, hl.y));
}

// ---------------------------------------------------------------------------
extern "C" void kernel_launch(void* const* d_in, const int* in_sizes, int n_in,
                              void* d_out, int out_size) {
    const float* x       = (const float*)d_in[0];
    const float* h_prev  = (const float*)d_in[1];
    const float* gate_w  = (const float*)d_in[2];
    const float* gate_b  = (const float*)d_in[3];
    const float* value_w = (const float*)d_in[4];
    const float* out_w   = (const float*)d_in[5];
    float* out = (float*)d_out;

    __half *p_gates, *p_v, *p_hh, *p_xh, *p_gwh, *p_vwh, *p_owh;
    cudaGetSymbolAddress((void**)&p_gates, g_gates);
    cudaGetSymbolAddress((void**)&p_v, g_v);
    cudaGetSymbolAddress((void**)&p_hh, g_hh);
    cudaGetSymbolAddress((void**)&p_xh, g_xh);
    cudaGetSymbolAddress((void**)&p_gwh, g_gwh);
    cudaGetSymbolAddress((void**)&p_vwh, g_vwh);
    cudaGetSymbolAddress((void**)&p_owh, g_owh);

    static bool attr_done = false;
    if (!attr_done) {
        cudaFuncSetAttribute(gemm_f16_mma<true>,
                             cudaFuncAttributeMaxDynamicSharedMemorySize,
                             NSTAGE * STG_BYTES * 2);
        cudaFuncSetAttribute(gemm_f16_mma<false>,
                             cudaFuncAttributeMaxDynamicSharedMemorySize,
                             NSTAGE * STG_BYTES * 2);
        attr_done = true;
    }
    const size_t SMEM = NSTAGE * STG_BYTES * 2;   // 65536

    // One fused fp16 conversion pass
    {
        int n = CVT_N_X + CVT_N_GW + CVT_N_VW + CVT_N_OW;
        convert_all<<<(n + 255) / 256, 256>>>(x, gate_w, value_w, out_w);
    }
    // Fused GEMM1: [gates | V] = x @ [gate_w | value_w]^T  (fp16 outputs)
    {
        dim3 grid(NGATES / 128 + HS / 128, M_TOT / 128);   // 24 x 128
        gemm_f16_mma<true><<<grid, 256, SMEM>>>(p_xh, p_gwh, p_vwh,
                                                p_gates, p_v,
                                                NGATES / 128, NGATES, HS, D_MODEL);
    }
    // Segmented scan
    {
        float* hlast = nullptr;
        if ((size_t)out_size >= (size_t)M_TOT * D_MODEL + BATCH * HS)
            hlast = out + (size_t)M_TOT * D_MODEL;
        scan_pass1<<<(BATCH * NSEG * HS) / 256, 256>>>(gate_b);
        scan_pass2<<<(BATCH * HS) / 256, 256>>>(h_prev, hlast);
        int n3 = M_TOT * (HS / 2);
        scan_pass3<<<(n3 + 255) / 256, 256>>>();
    }
    // GEMM2: y = h @ out_w^T  (fp32 output)
    {
        dim3 grid(D_MODEL / 128, M_TOT / 128);
        gemm_f16_mma<false><<<grid, 256, SMEM>>>(p_hh, p_owh, p_owh, out, out,
                                                 D_MODEL / 128, D_MODEL, D_MODEL, D_MODEL);
    }
}

// round 15
// speedup vs baseline: 1.2844x; 1.2844x over previous
#include <cuda_runtime.h>
#include <cuda_fp16.h>
#include <cstdint>

// Problem constants (GLALayer: B=4, T=4096, D_MODEL=1024, H=16, S=64)
#define D_MODEL 1024
#define T_LEN   4096
#define BATCH   4
#define M_TOT   (BATCH * T_LEN)   // 16384
#define HS      1024
#define NGATES  2048

#define NSEG    16
#define SEGLEN  (T_LEN / NSEG)    // 256

// Scratch (device globals)
__device__ __half g_gates[(size_t)M_TOT * NGATES];
__device__ __half g_v[(size_t)M_TOT * HS];
__device__ __half g_hl[(size_t)M_TOT * HS];     // fp16 local h (segment scan)
__device__ __half g_pc[(size_t)M_TOT * HS];     // fp16 cumulative prod of a
__device__ __half g_hh[(size_t)M_TOT * HS];     // fp16 final h (GEMM2 input)
__device__ __half g_xh[(size_t)M_TOT * D_MODEL];
__device__ __half g_gwh[(size_t)NGATES * D_MODEL];
__device__ __half g_vwh[(size_t)HS * D_MODEL];
__device__ __half g_owh[(size_t)D_MODEL * HS];
__device__ float g_segP[BATCH * NSEG * HS];
__device__ float g_segH[BATCH * NSEG * HS];
__device__ float g_segS[BATCH * NSEG * HS];

// ---------------------------------------------------------------------------
__device__ __forceinline__ uint32_t smem_u32(const void* p) {
    uint32_t a;
    asm("{ .reg .u64 t; cvta.to.shared.u64 t, %1; cvt.u32.u64 %0, t; }"
        : "=r"(a) : "l"(p));
    return a;
}

__device__ __forceinline__ void cpasync16(uint32_t dst, const void* src) {
    asm volatile("cp.async.cg.shared.global [%0], [%1], 16;" :: "r"(dst), "l"(src));
}
#define CP_COMMIT()  asm volatile("cp.async.commit_group;" ::: "memory")
#define CP_WAIT(n)   asm volatile("cp.async.wait_group %0;" :: "n"(n) : "memory")

// byte-offset swizzle (rows of 64 B) — R7 proven layout
__device__ __forceinline__ uint32_t sw64(uint32_t o) {
    return o ^ ((o >> 3) & 0x70);
}

__device__ __forceinline__ void mma_f16(float* c, const uint32_t* a, const uint32_t* b) {
    asm volatile(
        "mma.sync.aligned.m16n8k16.row.col.f32.f16.f16.f32 "
        "{%0,%1,%2,%3}, {%4,%5,%6,%7}, {%8,%9}, {%0,%1,%2,%3};"
        : "+f"(c[0]), "+f"(c[1]), "+f"(c[2]), "+f"(c[3])
        : "r"(a[0]), "r"(a[1]), "r"(a[2]), "r"(a[3]),
          "r"(b[0]), "r"(b[1]));
}

// ---------------------------------------------------------------------------
// TN GEMM fp16 mma.sync, fused dual-output — EXACT R7/R10 (692us) structure.
// CTA 128x128, 128 thr, warp tile 64x64. 4-stage cp.async, 32-half K stage.
// ---------------------------------------------------------------------------
#define KTH       32
#define STG_BYTES (128 * 64)         // 8192 per operand stage
#define NSTAGE    4
// dyn smem: NSTAGE * STG_BYTES * 2 = 65536 B

template<bool HALF_OUT>
__global__ void __launch_bounds__(128, 2)
gemm_f16_mma(const __half* __restrict__ A,
             const __half* __restrict__ B1, const __half* __restrict__ B2,
             void* __restrict__ C1, void* __restrict__ C2,
             int nsplit, int N1, int N2, int K) {
    extern __shared__ char smem[];
    const uint32_t sA_u = smem_u32(smem);
    const uint32_t sB_u = sA_u + NSTAGE * STG_BYTES;

    const int tid = threadIdx.x;
    const int lane = tid & 31;
    const int wid = tid >> 5;
    const int wm = (wid >> 1) * 64;
    const int wn = (wid & 1) * 64;
    const int g = lane >> 2;
    const int tg = lane & 3;

    const int bx = blockIdx.x, by = blockIdx.y;

    const __half* Bb;
    void* Cout;
    int Nout, colbase;
    if (bx < nsplit) {
        Bb = B1 + (size_t)bx * 128 * K;
        Cout = C1; Nout = N1; colbase = bx * 128;
    } else {
        Bb = B2 + (size_t)(bx - nsplit) * 128 * K;
        Cout = C2; Nout = N2; colbase = (bx - nsplit) * 128;
    }
    const __half* Ab = A + (size_t)by * 128 * K;

    float acc[4][8][4];
#pragma unroll
    for (int mi = 0; mi < 4; mi++)
#pragma unroll
        for (int ni = 0; ni < 8; ni++)
#pragma unroll
            for (int q = 0; q < 4; q++) acc[mi][ni][q] = 0.0f;

    const int NT = K / KTH;

    auto issue_stage = [&](int kt) {
        const int kof = kt * KTH;
        const uint32_t soff = (uint32_t)((kt & (NSTAGE - 1)) * STG_BYTES);
#pragma unroll
        for (int i = 0; i < 4; i++) {
            const int gid = tid + i * 128;      // 0..511
            const int row = gid >> 2;
            const int q = gid & 3;
            const uint32_t d = soff + sw64((uint32_t)(row * 64 + q * 16));
            cpasync16(sA_u + d, Ab + (size_t)row * K + kof + q * 8);
            cpasync16(sB_u + d, Bb + (size_t)row * K + kof + q * 8);
        }
        CP_COMMIT();
    };

    issue_stage(0);
    issue_stage(1);
    issue_stage(2);

    for (int kt = 0; kt < NT; kt++) {
        CP_WAIT(2);
        __syncthreads();

        const uint32_t aoff = sA_u + (uint32_t)((kt & (NSTAGE - 1)) * STG_BYTES);
        const uint32_t boff = sB_u + (uint32_t)((kt & (NSTAGE - 1)) * STG_BYTES);
#pragma unroll
        for (int ks = 0; ks < 2; ks++) {
            const int kb = ks * 32;             // 16 halfs = 32 B
            uint32_t af[4][4], bf[8][2];
#pragma unroll
            for (int mi = 0; mi < 4; mi++) {
                const int r = (wm + mi * 16 + g) * 64;
                const uint32_t o0 = (uint32_t)(r + kb + 4 * tg);
                af[mi][0] = *(const uint32_t*)__cvta_shared_to_generic(aoff + sw64(o0));
                af[mi][1] = *(const uint32_t*)__cvta_shared_to_generic(aoff + sw64(o0 + 512));
                af[mi][2] = *(const uint32_t*)__cvta_shared_to_generic(aoff + sw64(o0 + 16));
                af[mi][3] = *(const uint32_t*)__cvta_shared_to_generic(aoff + sw64(o0 + 528));
            }
#pragma unroll
            for (int ni = 0; ni < 8; ni++) {
                const int r = (wn + ni * 8 + g) * 64;
                const uint32_t o0 = (uint32_t)(r + kb + 4 * tg);
                bf[ni][0] = *(const uint32_t*)__cvta_shared_to_generic(boff + sw64(o0));
                bf[ni][1] = *(const uint32_t*)__cvta_shared_to_generic(boff + sw64(o0 + 16));
            }
#pragma unroll
            for (int mi = 0; mi < 4; mi++)
#pragma unroll
                for (int ni = 0; ni < 8; ni++)
                    mma_f16(acc[mi][ni], af[mi], bf[ni]);
        }
        __syncthreads();
        if (kt + 3 < NT) issue_stage(kt + 3);
    }

    // Epilogue
#pragma unroll
    for (int mi = 0; mi < 4; mi++) {
        const int row0 = by * 128 + wm + mi * 16 + g;
#pragma unroll
        for (int ni = 0; ni < 8; ni++) {
            const int col = colbase + wn + ni * 8 + 2 * tg;
            if (HALF_OUT) {
                __half* Ch = (__half*)Cout;
                *(__half2*)(Ch + (size_t)row0 * Nout + col) =
                    __floats2half2_rn(acc[mi][ni][0], acc[mi][ni][1]);
                *(__half2*)(Ch + (size_t)(row0 + 8) * Nout + col) =
                    __floats2half2_rn(acc[mi][ni][2], acc[mi][ni][3]);
            } else {
                float* Cf = (float*)Cout;
                *(float2*)(Cf + (size_t)row0 * Nout + col) =
                    make_float2(acc[mi][ni][0], acc[mi][ni][1]);
                *(float2*)(Cf + (size_t)(row0 + 8) * Nout + col) =
                    make_float2(acc[mi][ni][2], acc[mi][ni][3]);
            }
        }
    }
}

// ---------------------------------------------------------------------------
// One fused f32 -> f16 conversion, float4 (16B) granularity.
// ---------------------------------------------------------------------------
#define CVT_N_X   ((M_TOT * D_MODEL) / 4)
#define CVT_N_GW  ((NGATES * D_MODEL) / 4)
#define CVT_N_VW  ((HS * D_MODEL) / 4)
#define CVT_N_OW  ((D_MODEL * HS) / 4)

__global__ void convert_all(const float* __restrict__ x,
                            const float* __restrict__ gw,
                            const float* __restrict__ vw,
                            const float* __restrict__ ow) {
    int i = blockIdx.x * blockDim.x + threadIdx.x;
    const float* src;
    __half* dst;
    int off;
    if (i < CVT_N_X) {
        src = x; dst = g_xh; off = i;
    } else if (i < CVT_N_X + CVT_N_GW) {
        src = gw; dst = g_gwh; off = i - CVT_N_X;
    } else if (i < CVT_N_X + CVT_N_GW + CVT_N_VW) {
        src = vw; dst = g_vwh; off = i - CVT_N_X - CVT_N_GW;
    } else if (i < CVT_N_X + CVT_N_GW + CVT_N_VW + CVT_N_OW) {
        src = ow; dst = g_owh; off = i - CVT_N_X - CVT_N_GW - CVT_N_VW;
    } else {
        return;
    }
    float4 v = ((const float4*)src)[off];
    __half2 lo = __floats2half2_rn(v.x, v.y);
    __half2 hi = __floats2half2_rn(v.z, v.w);
    ((uint2*)dst)[off] = make_uint2(*(uint32_t*)&lo, *(uint32_t*)&hi);
}

// ---------------------------------------------------------------------------
// Segmented scan pass 1, half2-vectorized: each thread handles 2 adjacent j.
// a/bg/h/P in fp32 pairs; stores local h and cumulative a-product as fp16.
// ---------------------------------------------------------------------------
__global__ void scan_pass1(const float* __restrict__ gate_b) {
    int idx = blockIdx.x * blockDim.x + threadIdx.x;   // 0..32767
    int jp = idx & 511;             // half2 column pair
    int s = (idx >> 9) & (NSEG - 1);
    int b = idx >> (9 + 4);
    int j0 = jp * 2;
    size_t row0 = (size_t)b * T_LEN + (size_t)s * SEGLEN;
    const __half2* gp = (const __half2*)(g_gates + row0 * NGATES + j0);
    const __half2* vp = (const __half2*)(g_v + (row0 << 10) + j0);
    __half2* hl = (__half2*)(g_hl + (row0 << 10) + j0);
    __half2* pc = (__half2*)(g_pc + (row0 << 10) + j0);
    const float2 bfg = *(const float2*)(gate_b + j0);
    const float2 big = *(const float2*)(gate_b + HS + j0);
    float2 h = make_float2(0.0f, 0.0f), P = make_float2(1.0f, 1.0f);
#pragma unroll 4
    for (int t = 0; t < SEGLEN; t++) {
        float2 gf = __half22float2(gp[(size_t)t * (NGATES / 2)]);
        float2 gi = __half22float2(gp[(size_t)t * (NGATES / 2) + HS / 2]);
        float2 vv = __half22float2(vp[(size_t)t << 9]);
        float ax = 1.0f / (1.0f + __expf(-(gf.x + bfg.x)));
        float ay = 1.0f / (1.0f + __expf(-(gf.y + bfg.y)));
        float bx = 1.0f / (1.0f + __expf(-(gi.x + big.x)));
        float by = 1.0f / (1.0f + __expf(-(gi.y + big.y)));
        h.x = fmaf(ax, h.x, bx * vv.x);
        h.y = fmaf(ay, h.y, by * vv.y);
        P.x *= ax;
        P.y *= ay;
        hl[(size_t)t << 9] = __floats2half2_rn(h.x, h.y);
        pc[(size_t)t << 9] = __floats2half2_rn(P.x, P.y);
    }
    size_t ko = (((size_t)(b * NSEG + s)) << 10) + j0;
    *(float2*)(g_segP + ko) = P;
    *(float2*)(g_segH + ko) = h;
}

// ---------------------------------------------------------------------------
// Pass 2: warp-parallel affine scan over the 16 segments of each chain.
// 16 lanes per chain; Hillis-Steele composition (g∘f)=(Pg·Pf, Pg·Hf+Hg).
// Block 128 thr = 8 chains; grid 512.
// ---------------------------------------------------------------------------
__global__ void scan_pass2(const float* __restrict__ h0,
                           float* __restrict__ hlast) {
    int chain = blockIdx.x * 8 + (threadIdx.x >> 4);   // 0..4095
    int s = threadIdx.x & 15;
    int b = chain >> 10;
    int j = chain & 1023;
    int k = ((b * NSEG + s) << 10) + j;
    float P = g_segP[k];
    float H = g_segH[k];
#pragma unroll
    for (int d = 1; d < NSEG; d <<= 1) {
        float Pp = __shfl_up_sync(0xffffffffu, P, d, 16);
        float Hp = __shfl_up_sync(0xffffffffu, H, d, 16);
        if (s >= d) {
            H = fmaf(P, Hp, H);
            P *= Pp;
        }
    }
    // exclusive prefix for segment start state
    float Pe = __shfl_up_sync(0xffffffffu, P, 1, 16);
    float He = __shfl_up_sync(0xffffffffu, H, 1, 16);
    float h0v = h0[chain];
    g_segS[k] = (s == 0) ? h0v : fmaf(Pe, h0v, He);
    if (s == NSEG - 1 && hlast) hlast[chain] = fmaf(P, h0v, H);
}

// ---------------------------------------------------------------------------
// Pass 3: pure elementwise fixup, vectorized half2:
//   h_t = h_local_t + Pcum_t * h_segstart   -> fp16 for GEMM2.
// ---------------------------------------------------------------------------
__global__ void scan_pass3() {
    int i = blockIdx.x * blockDim.x + threadIdx.x;   // over half2 elements
    if (i >= M_TOT * (HS / 2)) return;
    int row = i >> 9;               // 0..16383
    int jp = i & 511;               // half2 pair index
    int b = row >> 12;
    int s = (row >> 8) & (NSEG - 1);
    float2 hs2 = *(const float2*)(g_segS + (((size_t)(b * NSEG + s)) << 10) + jp * 2);
    float2 hl = __half22float2(((const __half2*)g_hl)[i]);
    float2 p  = __half22float2(((const __half2*)g_pc)[i]);
    ((__half2*)g_hh)[i] = __floats2half2_rn(fmaf(p.x, hs2.x, hl.x),
                                            fmaf(p.y, hs2.y, hl.y));
}

// ---------------------------------------------------------------------------
extern "C" void kernel_launch(void* const* d_in, const int* in_sizes, int n_in,
                              void* d_out, int out_size) {
    const float* x       = (const float*)d_in[0];
    const float* h_prev  = (const float*)d_in[1];
    const float* gate_w  = (const float*)d_in[2];
    const float* gate_b  = (const float*)d_in[3];
    const float* value_w = (const float*)d_in[4];
    const float* out_w   = (const float*)d_in[5];
    float* out = (float*)d_out;

    __half *p_gates, *p_v, *p_hh, *p_xh, *p_gwh, *p_vwh, *p_owh;
    cudaGetSymbolAddress((void**)&p_gates, g_gates);
    cudaGetSymbolAddress((void**)&p_v, g_v);
    cudaGetSymbolAddress((void**)&p_hh, g_hh);
    cudaGetSymbolAddress((void**)&p_xh, g_xh);
    cudaGetSymbolAddress((void**)&p_gwh, g_gwh);
    cudaGetSymbolAddress((void**)&p_vwh, g_vwh);
    cudaGetSymbolAddress((void**)&p_owh, g_owh);

    static bool attr_done = false;
    if (!attr_done) {
        cudaFuncSetAttribute(gemm_f16_mma<true>,
                             cudaFuncAttributeMaxDynamicSharedMemorySize,
                             NSTAGE * STG_BYTES * 2);
        cudaFuncSetAttribute(gemm_f16_mma<false>,
                             cudaFuncAttributeMaxDynamicSharedMemorySize,
                             NSTAGE * STG_BYTES * 2);
        attr_done = true;
    }
    const size_t SMEM = NSTAGE * STG_BYTES * 2;   // 65536

    // One fused fp16 conversion pass (float4 granules)
    {
        int n = CVT_N_X + CVT_N_GW + CVT_N_VW + CVT_N_OW;
        convert_all<<<(n + 255) / 256, 256>>>(x, gate_w, value_w, out_w);
    }
    // Fused GEMM1: [gates | V] = x @ [gate_w | value_w]^T  (fp16 outputs)
    {
        dim3 grid(NGATES / 128 + HS / 128, M_TOT / 128);   // 24 x 128
        gemm_f16_mma<true><<<grid, 128, SMEM>>>(p_xh, p_gwh, p_vwh,
                                                p_gates, p_v,
                                                NGATES / 128, NGATES, HS, D_MODEL);
    }
    // Segmented scan
    {
        float* hlast = nullptr;
        if ((size_t)out_size >= (size_t)M_TOT * D_MODEL + BATCH * HS)
            hlast = out + (size_t)M_TOT * D_MODEL;
        scan_pass1<<<(BATCH * NSEG * (HS / 2)) / 256, 256>>>(gate_b);
        scan_pass2<<<(BATCH * HS) / 8, 128>>>(h_prev, hlast);
        int n3 = M_TOT * (HS / 2);
        scan_pass3<<<(n3 + 255) / 256, 256>>>();
    }
    // GEMM2: y = h @ out_w^T  (fp32 output)
    {
        dim3 grid(D_MODEL / 128, M_TOT / 128);
        gemm_f16_mma<false><<<grid, 128, SMEM>>>(p_hh, p_owh, p_owh, out, out,
                                                 D_MODEL / 128, D_MODEL, D_MODEL, D_MODEL);
    }
}